// round 8
// baseline (speedup 1.0000x reference)
#include <cuda_runtime.h>
#include <cuda_fp16.h>
#include <cstdint>
#include <math.h>

// Problem constants
#define BB 2
#define SS 2048
#define HH 1024
#define NH 16
#define HD 64
#define MM (BB*SS)   // 4096 tokens
#define SCALE 0.125f
#define LOG2E 1.4426950408889634f

// ---------------- scratch (device globals: allocation-free) ----------------
__device__ float g_WqF[HH*HH];
__device__ float g_WkF[HH*HH];
__device__ float g_bqF[HH];
__device__ float g_bkF[HH];
__device__ __half g_xh[MM*HH];
__device__ __half g_Qh[MM*HH];
__device__ __half g_Kh[MM*HH];
__device__ __half g_Vh[MM*HH];
__device__ __half g_Ch[MM*HH];
__device__ __half g_Bq[HH*HH];
__device__ __half g_Bk[HH*HH];
__device__ __half g_Bv[HH*HH];
__device__ __half g_Bo[HH*HH];

// ================= warp-level helpers (sm_80+ PTX) ==========================
static __device__ __forceinline__ uint32_t smem_u32(const void* p) {
  uint32_t a;
  asm("{ .reg .u64 t; cvta.to.shared.u64 t, %1; cvt.u32.u64 %0, t; }"
      : "=r"(a) : "l"(p));
  return a;
}
static __device__ __forceinline__ void ldsm4(uint32_t* r, uint32_t a) {
  asm volatile("ldmatrix.sync.aligned.m8n8.x4.shared.b16 {%0,%1,%2,%3}, [%4];"
               : "=r"(r[0]), "=r"(r[1]), "=r"(r[2]), "=r"(r[3]) : "r"(a));
}
static __device__ __forceinline__ void ldsm4t(uint32_t* r, uint32_t a) {
  asm volatile("ldmatrix.sync.aligned.m8n8.x4.trans.shared.b16 {%0,%1,%2,%3}, [%4];"
               : "=r"(r[0]), "=r"(r[1]), "=r"(r[2]), "=r"(r[3]) : "r"(a));
}
static __device__ __forceinline__ void mma16816h(float* c, const uint32_t* a,
                                                 uint32_t b0, uint32_t b1) {
  asm volatile(
    "mma.sync.aligned.m16n8k16.row.col.f32.f16.f16.f32 "
    "{%0,%1,%2,%3}, {%4,%5,%6,%7}, {%8,%9}, {%0,%1,%2,%3};"
    : "+f"(c[0]), "+f"(c[1]), "+f"(c[2]), "+f"(c[3])
    : "r"(a[0]), "r"(a[1]), "r"(a[2]), "r"(a[3]), "r"(b0), "r"(b1));
}
static __device__ __forceinline__ uint32_t pack_h2(float x, float y) {
  __half2 h = __floats2half2_rn(x, y);
  return *(uint32_t*)&h;
}
static __device__ __forceinline__ void cp16(uint32_t dst, const void* src) {
  asm volatile("cp.async.cg.shared.global [%0], [%1], 16;"
               :: "r"(dst), "l"(src) : "memory");
}
#define CP_COMMIT() asm volatile("cp.async.commit_group;" ::: "memory")
#define CP_WAIT(n)  asm volatile("cp.async.wait_group %0;" :: "n"(n) : "memory")

// ---------------- weight fold (batched q/k via z) -----------------------------
__global__ __launch_bounds__(256) void fold_w_kernel(
    const float* __restrict__ Wq, const float* __restrict__ Wql,
    const float* __restrict__ Wk, const float* __restrict__ Wkl,
    float* __restrict__ WqF, float* __restrict__ WkF) {
  const float* W  = blockIdx.z ? Wk  : Wq;
  const float* Wl = blockIdx.z ? Wkl : Wql;
  float* Wf       = blockIdx.z ? WkF : WqF;
  __shared__ float Ws[64][65];
  __shared__ float Ls[64][65];
  const int h  = blockIdx.x;
  const int i0 = blockIdx.y * 64;
  const int t  = threadIdx.x;
  for (int idx = t; idx < 64*64; idx += 256) {
    int rr = idx >> 6, cc = idx & 63;
    Ws[rr][cc] = W[(i0 + rr) * HH + h * 64 + cc];
    Ls[rr][cc] = Wl[rr * 64 + cc];
  }
  __syncthreads();
  const int ty = t >> 4, tx = t & 15;
  float acc[4][4];
#pragma unroll
  for (int i = 0; i < 4; i++)
#pragma unroll
    for (int j = 0; j < 4; j++) acc[i][j] = 0.f;
#pragma unroll 8
  for (int k = 0; k < 64; k++) {
    float a[4], b[4];
#pragma unroll
    for (int i = 0; i < 4; i++) a[i] = Ws[ty*4+i][k];
#pragma unroll
    for (int j = 0; j < 4; j++) b[j] = Ls[k][tx*4+j];
#pragma unroll
    for (int i = 0; i < 4; i++)
#pragma unroll
      for (int j = 0; j < 4; j++) acc[i][j] += a[i] * b[j];
  }
#pragma unroll
  for (int i = 0; i < 4; i++)
#pragma unroll
    for (int j = 0; j < 4; j++)
      Wf[(i0 + ty*4 + i) * HH + h * 64 + tx*4 + j] = acc[i][j];
}

__global__ void fold_b_kernel(
    const float* __restrict__ bq, const float* __restrict__ Wql,
    const float* __restrict__ bql,
    const float* __restrict__ bk, const float* __restrict__ Wkl,
    const float* __restrict__ bkl,
    float* __restrict__ bqF, float* __restrict__ bkF) {
  const float* b  = blockIdx.z ? bk  : bq;
  const float* Wl = blockIdx.z ? Wkl : Wql;
  const float* bl = blockIdx.z ? bkl : bql;
  float* bf       = blockIdx.z ? bkF : bqF;
  int idx = blockIdx.x * 256 + threadIdx.x;
  if (idx < HH) {
    int h = idx >> 6, r = idx & 63;
    float acc = bl[r];
    for (int d = 0; d < 64; d++) acc += b[h * 64 + d] * Wl[d * 64 + r];
    bf[idx] = acc;
  }
}

// ---------------- fp32 -> fp16 convert ----------------------------------------
__global__ __launch_bounds__(256) void cvt_kernel(
    const float* __restrict__ in, __half* __restrict__ out, int n4) {
  int i = blockIdx.x * 256 + threadIdx.x;
  if (i >= n4) return;
  float4 v = ((const float4*)in)[i];
  uint2 u;
  u.x = pack_h2(v.x, v.y);
  u.y = pack_h2(v.z, v.w);
  ((uint2*)out)[i] = u;
}

// ---------------- transpose to fp16 (batched 4 weights via z) -----------------
__global__ __launch_bounds__(256) void tcvt_kernel(
    const float* __restrict__ W0, const float* __restrict__ W1,
    const float* __restrict__ W2, const float* __restrict__ W3,
    __half* __restrict__ T0, __half* __restrict__ T1,
    __half* __restrict__ T2, __half* __restrict__ T3) {
  const int z = blockIdx.z;
  const float* W = (z == 0) ? W0 : (z == 1) ? W1 : (z == 2) ? W2 : W3;
  __half* Th     = (z == 0) ? T0 : (z == 1) ? T1 : (z == 2) ? T2 : T3;
  __shared__ float tile[32][33];
  const int k0 = blockIdx.y << 5, n0 = blockIdx.x << 5;
  const int tx = threadIdx.x & 31, ty = threadIdx.x >> 5;
#pragma unroll
  for (int i = 0; i < 4; i++)
    tile[ty + i*8][tx] = W[(size_t)(k0 + ty + i*8) * HH + n0 + tx];
  __syncthreads();
#pragma unroll
  for (int i = 0; i < 4; i++) {
    int r = ty + i*8;
    Th[(size_t)(n0 + r) * HH + k0 + tx] = __float2half_rn(tile[tx][r]);
  }
}

// ======= shared GEMM body: 128x128 tile, cp.async double buffer ==============
// 8 warps 4(m) x 2(n); warp tile 32x64. K-chunk 64.
// SMEM per stage: A 128x72 fp16 (18432) + B 128x72 (18432) = 36864; x2 = 73728.
#define GSMEM 73728
struct GemmAcc { float a[2][8][4]; };

static __device__ __forceinline__ void gemm_core(
    const __half* __restrict__ A, const __half* __restrict__ B,
    uint32_t smb, int m0, int n0, GemmAcc& C) {
  const int t = threadIdx.x, wid = t >> 5, l = t & 31;
  const int wm = wid >> 1, wn = wid & 1;
  const int lrow = t >> 1, lcb = (t & 1) << 2;
  const int arow_l = l & 15, acol_off = (l >> 4) << 3;
  const int brow_l = (l & 7) + ((l >> 4) << 3), bcol_off = ((l >> 3) & 1) << 3;

#define GLOAD(K0, ST) do { \
  const uint32_t base = smb + (uint32_t)(ST) * 36864; \
  _Pragma("unroll") \
  for (int j = 0; j < 4; j++) { \
    const int col = lcb + j; \
    cp16(base + (uint32_t)(lrow * 72 + col * 8) * 2, \
         A + (size_t)(m0 + lrow) * HH + (K0) + col * 8); \
    cp16(base + 18432u + (uint32_t)(lrow * 72 + col * 8) * 2, \
         B + (size_t)(n0 + lrow) * HH + (K0) + col * 8); \
  } } while (0)

  GLOAD(0, 0);
  CP_COMMIT();
  for (int ch = 0; ch < 16; ch++) {
    const int st = ch & 1;
    __syncthreads();
    if (ch < 15) { GLOAD((ch + 1) << 6, st ^ 1); CP_COMMIT(); }
    if (ch < 15) { CP_WAIT(1); } else { CP_WAIT(0); }
    __syncthreads();
    const uint32_t sbase = smb + (uint32_t)st * 36864;
#pragma unroll
    for (int kc = 0; kc < 4; kc++) {
      uint32_t ah[2][4];
#pragma unroll
      for (int mt = 0; mt < 2; mt++)
        ldsm4(ah[mt], sbase + (uint32_t)(((wm << 5) + (mt << 4) + arow_l) * 72 +
                                         (kc << 4) + acol_off) * 2);
      uint32_t bh[16];
#pragma unroll
      for (int np = 0; np < 4; np++)
        ldsm4(bh + np * 4,
              sbase + 18432u +
              (uint32_t)(((wn << 6) + (np << 4) + brow_l) * 72 +
                         (kc << 4) + bcol_off) * 2);
#pragma unroll
      for (int mt = 0; mt < 2; mt++)
#pragma unroll
        for (int nt = 0; nt < 8; nt++)
          mma16816h(C.a[mt][nt], ah[mt], bh[nt*2], bh[nt*2+1]);
    }
  }
#undef GLOAD
}

// ---------------- merged QKV projection GEMM (fp16 out) -----------------------
__global__ __launch_bounds__(256, 2) void qkv_hmma(
    const __half* __restrict__ Ah,
    const __half* __restrict__ Bq, const __half* __restrict__ Bk,
    const __half* __restrict__ Bv,
    const float* __restrict__ biq, const float* __restrict__ bik,
    const float* __restrict__ biv,
    __half* __restrict__ Oq, __half* __restrict__ Ok, __half* __restrict__ Ov) {
  extern __shared__ char sm8[];
  const uint32_t smb = smem_u32(sm8);
  const int z = blockIdx.z;
  const __half* B = (z == 0) ? Bq : (z == 1) ? Bk : Bv;
  const float* bias = (z == 0) ? biq : (z == 1) ? bik : biv;
  __half* H = (z == 0) ? Oq : (z == 1) ? Ok : Ov;
  const int n0 = blockIdx.x << 7, m0 = blockIdx.y << 7;
  const int t = threadIdx.x, wid = t >> 5, l = t & 31;
  const int wm = wid >> 1, wn = wid & 1;

  GemmAcc C;
#pragma unroll
  for (int a = 0; a < 2; a++)
#pragma unroll
    for (int b = 0; b < 8; b++)
#pragma unroll
      for (int c = 0; c < 4; c++) C.a[a][b][c] = 0.f;

  gemm_core(Ah, B, smb, m0, n0, C);

#pragma unroll
  for (int mt = 0; mt < 2; mt++) {
    const int r1 = m0 + (wm << 5) + (mt << 4) + (l >> 2);
    const int r2 = r1 + 8;
#pragma unroll
    for (int nt = 0; nt < 8; nt++) {
      const int col = n0 + (wn << 6) + (nt << 3) + ((l & 3) << 1);
      const float2 bb = *(const float2*)&bias[col];
      *(uint32_t*)&H[(size_t)r1 * HH + col] =
          pack_h2(C.a[mt][nt][0] + bb.x, C.a[mt][nt][1] + bb.y);
      *(uint32_t*)&H[(size_t)r2 * HH + col] =
          pack_h2(C.a[mt][nt][2] + bb.x, C.a[mt][nt][3] + bb.y);
    }
  }
}

// ---------------- output projection GEMM (fp32 out) ---------------------------
__global__ __launch_bounds__(256, 2) void gemmo_hmma(
    const __half* __restrict__ Ah, const __half* __restrict__ B,
    const float* __restrict__ bias, float* __restrict__ Cf) {
  extern __shared__ char sm8[];
  const uint32_t smb = smem_u32(sm8);
  const int n0 = blockIdx.x << 7, m0 = blockIdx.y << 7;
  const int t = threadIdx.x, wid = t >> 5, l = t & 31;
  const int wm = wid >> 1, wn = wid & 1;

  GemmAcc C;
#pragma unroll
  for (int a = 0; a < 2; a++)
#pragma unroll
    for (int b = 0; b < 8; b++)
#pragma unroll
      for (int c = 0; c < 4; c++) C.a[a][b][c] = 0.f;

  gemm_core(Ah, B, smb, m0, n0, C);

#pragma unroll
  for (int mt = 0; mt < 2; mt++) {
    const int r1 = m0 + (wm << 5) + (mt << 4) + (l >> 2);
    const int r2 = r1 + 8;
#pragma unroll
    for (int nt = 0; nt < 8; nt++) {
      const int col = n0 + (wn << 6) + (nt << 3) + ((l & 3) << 1);
      const float2 bb = *(const float2*)&bias[col];
      *(float2*)&Cf[(size_t)r1 * HH + col] =
          make_float2(C.a[mt][nt][0] + bb.x, C.a[mt][nt][1] + bb.y);
      *(float2*)&Cf[(size_t)r2 * HH + col] =
          make_float2(C.a[mt][nt][2] + bb.x, C.a[mt][nt][3] + bb.y);
    }
  }
}

// ---------------- fp16 flash attention: 128q tile, cp.async double buffer -----
// SMEM: stage{0,1}: K 9216 + V 9216 (=18432 each); mask 8192. Total 45056.
#define ASMEM 45056
__global__ __launch_bounds__(256, 2) void attn_hmma(
    const __half* __restrict__ Qh, const __half* __restrict__ Kh,
    const __half* __restrict__ Vh, const float* __restrict__ mask,
    __half* __restrict__ Oh) {
  extern __shared__ char sm8[];
  const uint32_t smb = smem_u32(sm8);
  float* smask = (float*)(sm8 + 36864);
  const int t = threadIdx.x, wid = t >> 5, l = t & 31;
  const int qt = blockIdx.x, h = blockIdx.y, b = blockIdx.z;
  const int hc = h << 6, tokbase = b * SS, q0 = qt << 7;

  // stage mask * LOG2E (once)
  for (int i = t; i < SS / 4; i += 256) {
    float4 mv = ((const float4*)(mask + b * SS))[i];
    mv.x *= LOG2E; mv.y *= LOG2E; mv.z *= LOG2E; mv.w *= LOG2E;
    ((float4*)smask)[i] = mv;
  }

  // Q fragments resident in registers (warp w -> q rows [w*16, w*16+16))
  const int grow0 = tokbase + q0 + (wid << 4) + (l >> 2);
  uint32_t qh[4][4];
#pragma unroll
  for (int kc = 0; kc < 4; kc++)
#pragma unroll
    for (int j = 0; j < 4; j++) {
      const int row = grow0 + ((j & 1) << 3);
      const int k = (kc << 4) + ((l & 3) << 1) + ((j >> 1) << 3);
      qh[kc][j] = *(const uint32_t*)(Qh + (size_t)row * HH + hc + k);
    }

  float o[8][4];
#pragma unroll
  for (int i = 0; i < 8; i++)
#pragma unroll
    for (int j = 0; j < 4; j++) o[i][j] = 0.f;
  float m1 = -1e30f, m2 = -1e30f, lsum1 = 0.f, lsum2 = 0.f;

  const int lrow = t >> 2, lcb = (t & 3) << 1;   // 64 rows x {2 cols of 16B}
  const int krow = (l & 7) + ((l >> 4) << 3);
  const int kcol_off = ((l >> 3) & 1) << 3;
  const int vrow = (l & 7) + (((l >> 3) & 1) << 3);
  const int vcol = (l >> 4) << 3;
  const float sl = SCALE * LOG2E;

#define ALOAD(K0, ST) do { \
  const uint32_t base = smb + (uint32_t)(ST) * 18432; \
  const size_t grow = (size_t)(tokbase + (K0) + lrow) * HH + hc; \
  _Pragma("unroll") \
  for (int j = 0; j < 2; j++) { \
    const int col = lcb + j; \
    const uint32_t so = (uint32_t)(lrow * 72 + col * 8) * 2; \
    cp16(base + so,         Kh + grow + col * 8); \
    cp16(base + 9216u + so, Vh + grow + col * 8); \
  } } while (0)

  ALOAD(0, 0);
  CP_COMMIT();
  for (int kt = 0; kt < SS / 64; kt++) {
    const int k0 = kt << 6;
    const int st = kt & 1;
    __syncthreads();
    if (kt < SS/64 - 1) { ALOAD(k0 + 64, st ^ 1); CP_COMMIT(); }
    if (kt < SS/64 - 1) { CP_WAIT(1); } else { CP_WAIT(0); }
    __syncthreads();
    const uint32_t sbase = smb + (uint32_t)st * 18432;

    // ---- S = Q @ K^T (single fp16) ----
    float sc[8][4];
#pragma unroll
    for (int i = 0; i < 8; i++)
#pragma unroll
      for (int j = 0; j < 4; j++) sc[i][j] = 0.f;
#pragma unroll
    for (int kc = 0; kc < 4; kc++) {
      uint32_t kh[16];
#pragma unroll
      for (int np = 0; np < 4; np++)
        ldsm4(kh + np * 4,
              sbase + (uint32_t)(((np << 4) + krow) * 72 +
                                 (kc << 4) + kcol_off) * 2);
#pragma unroll
      for (int nt = 0; nt < 8; nt++)
        mma16816h(sc[nt], qh[kc], kh[nt*2], kh[nt*2+1]);
    }

    // ---- online softmax (log2 domain) ----
    float nm1 = m1, nm2 = m2;
#pragma unroll
    for (int nt = 0; nt < 8; nt++) {
      const float2 mv = *(const float2*)&smask[k0 + (nt << 3) + ((l & 3) << 1)];
      sc[nt][0] = sc[nt][0] * sl + mv.x;
      sc[nt][1] = sc[nt][1] * sl + mv.y;
      sc[nt][2] = sc[nt][2] * sl + mv.x;
      sc[nt][3] = sc[nt][3] * sl + mv.y;
      nm1 = fmaxf(nm1, fmaxf(sc[nt][0], sc[nt][1]));
      nm2 = fmaxf(nm2, fmaxf(sc[nt][2], sc[nt][3]));
    }
    nm1 = fmaxf(nm1, __shfl_xor_sync(0xffffffffu, nm1, 1));
    nm1 = fmaxf(nm1, __shfl_xor_sync(0xffffffffu, nm1, 2));
    nm2 = fmaxf(nm2, __shfl_xor_sync(0xffffffffu, nm2, 1));
    nm2 = fmaxf(nm2, __shfl_xor_sync(0xffffffffu, nm2, 2));
    const float a1 = exp2f(m1 - nm1), a2 = exp2f(m2 - nm2);
    m1 = nm1; m2 = nm2;
    float rs1 = 0.f, rs2 = 0.f;
#pragma unroll
    for (int nt = 0; nt < 8; nt++) {
      sc[nt][0] = exp2f(sc[nt][0] - m1);
      sc[nt][1] = exp2f(sc[nt][1] - m1);
      sc[nt][2] = exp2f(sc[nt][2] - m2);
      sc[nt][3] = exp2f(sc[nt][3] - m2);
      rs1 += sc[nt][0] + sc[nt][1];
      rs2 += sc[nt][2] + sc[nt][3];
      o[nt][0] *= a1; o[nt][1] *= a1; o[nt][2] *= a2; o[nt][3] *= a2;
    }
    lsum1 = lsum1 * a1 + rs1;
    lsum2 = lsum2 * a2 + rs2;

    // ---- O += P @ V (single fp16) ----
#pragma unroll
    for (int kc2 = 0; kc2 < 4; kc2++) {
      uint32_t ph[4];
      ph[0] = pack_h2(sc[2*kc2][0],   sc[2*kc2][1]);
      ph[1] = pack_h2(sc[2*kc2][2],   sc[2*kc2][3]);
      ph[2] = pack_h2(sc[2*kc2+1][0], sc[2*kc2+1][1]);
      ph[3] = pack_h2(sc[2*kc2+1][2], sc[2*kc2+1][3]);
#pragma unroll
      for (int dp = 0; dp < 4; dp++) {
        uint32_t vh[4];
        ldsm4t(vh, sbase + 9216u +
                   (uint32_t)(((kc2 << 4) + vrow) * 72 +
                              (dp << 4) + vcol) * 2);
        mma16816h(o[2*dp],   ph, vh[0], vh[1]);
        mma16816h(o[2*dp+1], ph, vh[2], vh[3]);
      }
    }
  }
#undef ALOAD

  // ---- epilogue: normalize + store CTX fp16 ----
  lsum1 += __shfl_xor_sync(0xffffffffu, lsum1, 1);
  lsum1 += __shfl_xor_sync(0xffffffffu, lsum1, 2);
  lsum2 += __shfl_xor_sync(0xffffffffu, lsum2, 1);
  lsum2 += __shfl_xor_sync(0xffffffffu, lsum2, 2);
  const float i1 = 1.f / lsum1, i2 = 1.f / lsum2;
  const int r1 = grow0, r2 = grow0 + 8;
#pragma unroll
  for (int nt = 0; nt < 8; nt++) {
    const int col = hc + (nt << 3) + ((l & 3) << 1);
    *(uint32_t*)&Oh[(size_t)r1 * HH + col] =
        pack_h2(o[nt][0] * i1, o[nt][1] * i1);
    *(uint32_t*)&Oh[(size_t)r2 * HH + col] =
        pack_h2(o[nt][2] * i2, o[nt][3] * i2);
  }
}

// ---------------- launch ------------------------------------------------------
extern "C" void kernel_launch(void* const* d_in, const int* in_sizes, int n_in,
                              void* d_out, int out_size) {
  const float* x    = (const float*)d_in[0];
  const float* mask = (const float*)d_in[1];
  const float* Wq   = (const float*)d_in[2];
  const float* bq   = (const float*)d_in[3];
  const float* Wk   = (const float*)d_in[4];
  const float* bk   = (const float*)d_in[5];
  const float* Wv   = (const float*)d_in[6];
  const float* bv   = (const float*)d_in[7];
  const float* Wql  = (const float*)d_in[8];
  const float* bql  = (const float*)d_in[9];
  const float* Wkl  = (const float*)d_in[10];
  const float* bkl  = (const float*)d_in[11];
  const float* Wo   = (const float*)d_in[12];
  const float* bo   = (const float*)d_in[13];
  float* out = (float*)d_out;

  float *WqF, *WkF, *bqF, *bkF;
  cudaGetSymbolAddress((void**)&WqF, g_WqF);
  cudaGetSymbolAddress((void**)&WkF, g_WkF);
  cudaGetSymbolAddress((void**)&bqF, g_bqF);
  cudaGetSymbolAddress((void**)&bkF, g_bkF);
  __half *xh, *Qhp, *Khp, *Vhp, *Chp, *Bqp, *Bkp, *Bvp, *Bop;
  cudaGetSymbolAddress((void**)&xh, g_xh);
  cudaGetSymbolAddress((void**)&Qhp, g_Qh);
  cudaGetSymbolAddress((void**)&Khp, g_Kh);
  cudaGetSymbolAddress((void**)&Vhp, g_Vh);
  cudaGetSymbolAddress((void**)&Chp, g_Ch);
  cudaGetSymbolAddress((void**)&Bqp, g_Bq);
  cudaGetSymbolAddress((void**)&Bkp, g_Bk);
  cudaGetSymbolAddress((void**)&Bvp, g_Bv);
  cudaGetSymbolAddress((void**)&Bop, g_Bo);

  cudaFuncSetAttribute(qkv_hmma,
                       cudaFuncAttributeMaxDynamicSharedMemorySize, GSMEM);
  cudaFuncSetAttribute(gemmo_hmma,
                       cudaFuncAttributeMaxDynamicSharedMemorySize, GSMEM);
  cudaFuncSetAttribute(attn_hmma,
                       cudaFuncAttributeMaxDynamicSharedMemorySize, ASMEM);

  // 1. fold low-rank projections into token-GEMM weights (batched q/k)
  fold_w_kernel<<<dim3(NH, 16, 2), 256>>>(Wq, Wql, Wk, Wkl, WqF, WkF);
  fold_b_kernel<<<dim3(4, 1, 2), 256>>>(bq, Wql, bql, bk, Wkl, bkl, bqF, bkF);

  // 2. x -> fp16; weights -> transposed fp16 (batched 4)
  cvt_kernel<<<(MM*HH/4 + 255)/256, 256>>>(x, xh, MM*HH/4);
  tcvt_kernel<<<dim3(32, 32, 4), 256>>>(WqF, WkF, Wv, Wo, Bqp, Bkp, Bvp, Bop);

  // 3. merged QKV projection (128x128 tiles, cp.async double buffer)
  qkv_hmma<<<dim3(8, 32, 3), 256, GSMEM>>>(
      xh, Bqp, Bkp, Bvp, bqF, bkF, bv, Qhp, Khp, Vhp);

  // 4. fp16 flash attention (128-q tiles) -> CTX fp16
  attn_hmma<<<dim3(SS/128, NH, BB), 256, ASMEM>>>(Qhp, Khp, Vhp, mask, Chp);

  // 5. output projection (fp32 out)
  gemmo_hmma<<<dim3(8, 32), 256, GSMEM>>>(Chp, Bop, bo, out);
}

// round 9
// speedup vs baseline: 1.0800x; 1.0800x over previous
#include <cuda_runtime.h>
#include <cuda_fp16.h>
#include <cstdint>
#include <math.h>

// Problem constants
#define BB 2
#define SS 2048
#define HH 1024
#define NH 16
#define HD 64
#define MM (BB*SS)   // 4096 tokens
#define SCALE 0.125f
#define LOG2E 1.4426950408889634f

// ---------------- scratch (device globals: allocation-free) ----------------
__device__ float g_WqF[HH*HH];
__device__ float g_WkF[HH*HH];
__device__ float g_bqF[HH];
__device__ float g_bkF[HH];
__device__ __half g_xh[MM*HH];
__device__ __half g_Qh[MM*HH];
__device__ __half g_Kh[MM*HH];
__device__ __half g_Vh[MM*HH];
__device__ __half g_Ch[MM*HH];
__device__ __half g_Bq[HH*HH];
__device__ __half g_Bk[HH*HH];
__device__ __half g_Bv[HH*HH];
__device__ __half g_Bo[HH*HH];

// ================= warp-level MMA helpers (sm_80+ PTX) ======================
static __device__ __forceinline__ uint32_t smem_u32(const void* p) {
  uint32_t a;
  asm("{ .reg .u64 t; cvta.to.shared.u64 t, %1; cvt.u32.u64 %0, t; }"
      : "=r"(a) : "l"(p));
  return a;
}
static __device__ __forceinline__ void ldsm4(uint32_t* r, uint32_t a) {
  asm volatile("ldmatrix.sync.aligned.m8n8.x4.shared.b16 {%0,%1,%2,%3}, [%4];"
               : "=r"(r[0]), "=r"(r[1]), "=r"(r[2]), "=r"(r[3]) : "r"(a));
}
static __device__ __forceinline__ void ldsm4t(uint32_t* r, uint32_t a) {
  asm volatile("ldmatrix.sync.aligned.m8n8.x4.trans.shared.b16 {%0,%1,%2,%3}, [%4];"
               : "=r"(r[0]), "=r"(r[1]), "=r"(r[2]), "=r"(r[3]) : "r"(a));
}
static __device__ __forceinline__ void mma16816h(float* c, const uint32_t* a,
                                                 uint32_t b0, uint32_t b1) {
  asm volatile(
    "mma.sync.aligned.m16n8k16.row.col.f32.f16.f16.f32 "
    "{%0,%1,%2,%3}, {%4,%5,%6,%7}, {%8,%9}, {%0,%1,%2,%3};"
    : "+f"(c[0]), "+f"(c[1]), "+f"(c[2]), "+f"(c[3])
    : "r"(a[0]), "r"(a[1]), "r"(a[2]), "r"(a[3]), "r"(b0), "r"(b1));
}
static __device__ __forceinline__ uint32_t pack_h2(float x, float y) {
  __half2 h = __floats2half2_rn(x, y);
  return *(uint32_t*)&h;
}

// ---------------- weight fold (batched q/k via z) -----------------------------
__global__ __launch_bounds__(256) void fold_w_kernel(
    const float* __restrict__ Wq, const float* __restrict__ Wql,
    const float* __restrict__ Wk, const float* __restrict__ Wkl,
    float* __restrict__ WqF, float* __restrict__ WkF) {
  const float* W  = blockIdx.z ? Wk  : Wq;
  const float* Wl = blockIdx.z ? Wkl : Wql;
  float* Wf       = blockIdx.z ? WkF : WqF;
  __shared__ float Ws[64][65];
  __shared__ float Ls[64][65];
  const int h  = blockIdx.x;
  const int i0 = blockIdx.y * 64;
  const int t  = threadIdx.x;
  for (int idx = t; idx < 64*64; idx += 256) {
    int rr = idx >> 6, cc = idx & 63;
    Ws[rr][cc] = W[(i0 + rr) * HH + h * 64 + cc];
    Ls[rr][cc] = Wl[rr * 64 + cc];
  }
  __syncthreads();
  const int ty = t >> 4, tx = t & 15;
  float acc[4][4];
#pragma unroll
  for (int i = 0; i < 4; i++)
#pragma unroll
    for (int j = 0; j < 4; j++) acc[i][j] = 0.f;
#pragma unroll 8
  for (int k = 0; k < 64; k++) {
    float a[4], b[4];
#pragma unroll
    for (int i = 0; i < 4; i++) a[i] = Ws[ty*4+i][k];
#pragma unroll
    for (int j = 0; j < 4; j++) b[j] = Ls[k][tx*4+j];
#pragma unroll
    for (int i = 0; i < 4; i++)
#pragma unroll
      for (int j = 0; j < 4; j++) acc[i][j] += a[i] * b[j];
  }
#pragma unroll
  for (int i = 0; i < 4; i++)
#pragma unroll
    for (int j = 0; j < 4; j++)
      Wf[(i0 + ty*4 + i) * HH + h * 64 + tx*4 + j] = acc[i][j];
}

__global__ void fold_b_kernel(
    const float* __restrict__ bq, const float* __restrict__ Wql,
    const float* __restrict__ bql,
    const float* __restrict__ bk, const float* __restrict__ Wkl,
    const float* __restrict__ bkl,
    float* __restrict__ bqF, float* __restrict__ bkF) {
  const float* b  = blockIdx.z ? bk  : bq;
  const float* Wl = blockIdx.z ? Wkl : Wql;
  const float* bl = blockIdx.z ? bkl : bql;
  float* bf       = blockIdx.z ? bkF : bqF;
  int idx = blockIdx.x * 256 + threadIdx.x;
  if (idx < HH) {
    int h = idx >> 6, r = idx & 63;
    float acc = bl[r];
    for (int d = 0; d < 64; d++) acc += b[h * 64 + d] * Wl[d * 64 + r];
    bf[idx] = acc;
  }
}

// ---------------- fp32 -> fp16 convert ----------------------------------------
__global__ __launch_bounds__(256) void cvt_kernel(
    const float* __restrict__ in, __half* __restrict__ out, int n4) {
  int i = blockIdx.x * 256 + threadIdx.x;
  if (i >= n4) return;
  float4 v = ((const float4*)in)[i];
  uint2 u;
  u.x = pack_h2(v.x, v.y);
  u.y = pack_h2(v.z, v.w);
  ((uint2*)out)[i] = u;
}

// ---------------- transpose to fp16 (batched 4 weights via z) -----------------
__global__ __launch_bounds__(256) void tcvt_kernel(
    const float* __restrict__ W0, const float* __restrict__ W1,
    const float* __restrict__ W2, const float* __restrict__ W3,
    __half* __restrict__ T0, __half* __restrict__ T1,
    __half* __restrict__ T2, __half* __restrict__ T3) {
  const int z = blockIdx.z;
  const float* W = (z == 0) ? W0 : (z == 1) ? W1 : (z == 2) ? W2 : W3;
  __half* Th     = (z == 0) ? T0 : (z == 1) ? T1 : (z == 2) ? T2 : T3;
  __shared__ float tile[32][33];
  const int k0 = blockIdx.y << 5, n0 = blockIdx.x << 5;
  const int tx = threadIdx.x & 31, ty = threadIdx.x >> 5;
#pragma unroll
  for (int i = 0; i < 4; i++)
    tile[ty + i*8][tx] = W[(size_t)(k0 + ty + i*8) * HH + n0 + tx];
  __syncthreads();
#pragma unroll
  for (int i = 0; i < 4; i++) {
    int r = ty + i*8;
    Th[(size_t)(n0 + r) * HH + k0 + tx] = __float2half_rn(tile[tx][r]);
  }
}

// ============= shared GEMM body (A fp16 x B fp16, 1 MMA per frag) ============
// Block tile 128x64, K-chunk 64. 8 warps 4(m)x2(n), warp tile 32x32.
// SMEM: A 18432 + B 9216 = 27648.  (proven R7 config)
#define GSMEM 27648
struct GemmAcc { float a[2][4][4]; };

static __device__ __forceinline__ void gemm_core(
    const __half* __restrict__ A, const __half* __restrict__ B,
    char* sm8, uint32_t smb, int m0, int n0, GemmAcc& C) {
  const int t = threadIdx.x, wid = t >> 5, l = t & 31;
  const int wm = wid >> 1, wn = wid & 1;
  const int lr = t >> 3, lc = t & 7;
  const int arow_l = l & 15, acol_off = (l >> 4) << 3;
  const int brow_l = (l & 7) + ((l >> 4) << 3), bcol_off = ((l >> 3) & 1) << 3;

  uint4 pa0[4], pb0[2];
#define GLOAD(K0) do { \
  _Pragma("unroll") \
  for (int i = 0; i < 4; i++) { \
    const size_t g = (size_t)(m0 + lr + (i << 5)) * HH + (K0) + lc * 8; \
    pa0[i] = *(const uint4*)(A + g); \
  } \
  _Pragma("unroll") \
  for (int i = 0; i < 2; i++) { \
    const size_t g = (size_t)(n0 + lr + (i << 5)) * HH + (K0) + lc * 8; \
    pb0[i] = *(const uint4*)(B + g); \
  } } while (0)

  GLOAD(0);
  for (int ch = 0; ch < 16; ch++) {
    __syncthreads();
#pragma unroll
    for (int i = 0; i < 4; i++) {
      const uint32_t so = (uint32_t)((lr + (i << 5)) * 72 + lc * 8) * 2;
      *(uint4*)(sm8 + so) = pa0[i];
    }
#pragma unroll
    for (int i = 0; i < 2; i++) {
      const uint32_t so = (uint32_t)((lr + (i << 5)) * 72 + lc * 8) * 2;
      *(uint4*)(sm8 + 18432 + so) = pb0[i];
    }
    __syncthreads();
    if (ch < 15) GLOAD((ch + 1) << 6);
#pragma unroll
    for (int kc = 0; kc < 4; kc++) {
      uint32_t ah[2][4];
#pragma unroll
      for (int mt = 0; mt < 2; mt++) {
        const uint32_t sa =
            smb + (uint32_t)(((wm << 5) + (mt << 4) + arow_l) * 72 +
                             (kc << 4) + acol_off) * 2;
        ldsm4(ah[mt], sa);
      }
      uint32_t bh[8];
#pragma unroll
      for (int np = 0; np < 2; np++) {
        const uint32_t sb =
            smb + 18432 + (uint32_t)(((wn << 5) + (np << 4) + brow_l) * 72 +
                                     (kc << 4) + bcol_off) * 2;
        ldsm4(bh + np * 4, sb);
      }
#pragma unroll
      for (int mt = 0; mt < 2; mt++)
#pragma unroll
        for (int nt = 0; nt < 4; nt++)
          mma16816h(C.a[mt][nt], ah[mt], bh[nt*2], bh[nt*2+1]);
    }
  }
#undef GLOAD
}

// ---------------- merged QKV projection GEMM (fp16 out) -----------------------
__global__ __launch_bounds__(256, 2) void qkv_hmma(
    const __half* __restrict__ Ah,
    const __half* __restrict__ Bq, const __half* __restrict__ Bk,
    const __half* __restrict__ Bv,
    const float* __restrict__ biq, const float* __restrict__ bik,
    const float* __restrict__ biv,
    __half* __restrict__ Oq, __half* __restrict__ Ok, __half* __restrict__ Ov) {
  extern __shared__ char sm8[];
  const uint32_t smb = smem_u32(sm8);
  const int z = blockIdx.z;
  const __half* B = (z == 0) ? Bq : (z == 1) ? Bk : Bv;
  const float* bias = (z == 0) ? biq : (z == 1) ? bik : biv;
  __half* H = (z == 0) ? Oq : (z == 1) ? Ok : Ov;
  const int n0 = blockIdx.x << 6, m0 = blockIdx.y << 7;
  const int t = threadIdx.x, wid = t >> 5, l = t & 31;
  const int wm = wid >> 1, wn = wid & 1;

  GemmAcc C;
#pragma unroll
  for (int a = 0; a < 2; a++)
#pragma unroll
    for (int b = 0; b < 4; b++)
#pragma unroll
      for (int c = 0; c < 4; c++) C.a[a][b][c] = 0.f;

  gemm_core(Ah, B, sm8, smb, m0, n0, C);

#pragma unroll
  for (int mt = 0; mt < 2; mt++) {
    const int r1 = m0 + (wm << 5) + (mt << 4) + (l >> 2);
    const int r2 = r1 + 8;
#pragma unroll
    for (int nt = 0; nt < 4; nt++) {
      const int col = n0 + (wn << 5) + (nt << 3) + ((l & 3) << 1);
      const float2 bb = *(const float2*)&bias[col];
      *(uint32_t*)&H[(size_t)r1 * HH + col] =
          pack_h2(C.a[mt][nt][0] + bb.x, C.a[mt][nt][1] + bb.y);
      *(uint32_t*)&H[(size_t)r2 * HH + col] =
          pack_h2(C.a[mt][nt][2] + bb.x, C.a[mt][nt][3] + bb.y);
    }
  }
}

// ---------------- output projection GEMM (fp32 out) ---------------------------
__global__ __launch_bounds__(256, 2) void gemmo_hmma(
    const __half* __restrict__ Ah, const __half* __restrict__ B,
    const float* __restrict__ bias, float* __restrict__ Cf) {
  extern __shared__ char sm8[];
  const uint32_t smb = smem_u32(sm8);
  const int n0 = blockIdx.x << 6, m0 = blockIdx.y << 7;
  const int t = threadIdx.x, wid = t >> 5, l = t & 31;
  const int wm = wid >> 1, wn = wid & 1;

  GemmAcc C;
#pragma unroll
  for (int a = 0; a < 2; a++)
#pragma unroll
    for (int b = 0; b < 4; b++)
#pragma unroll
      for (int c = 0; c < 4; c++) C.a[a][b][c] = 0.f;

  gemm_core(Ah, B, sm8, smb, m0, n0, C);

#pragma unroll
  for (int mt = 0; mt < 2; mt++) {
    const int r1 = m0 + (wm << 5) + (mt << 4) + (l >> 2);
    const int r2 = r1 + 8;
#pragma unroll
    for (int nt = 0; nt < 4; nt++) {
      const int col = n0 + (wn << 5) + (nt << 3) + ((l & 3) << 1);
      const float2 bb = *(const float2*)&bias[col];
      *(float2*)&Cf[(size_t)r1 * HH + col] =
          make_float2(C.a[mt][nt][0] + bb.x, C.a[mt][nt][1] + bb.y);
      *(float2*)&Cf[(size_t)r2 * HH + col] =
          make_float2(C.a[mt][nt][2] + bb.x, C.a[mt][nt][3] + bb.y);
    }
  }
}

// ---------------- fp16 flash attention: 128-q tile, 8 warps, reg-prefetch -----
// Warp w owns q rows [16w, 16w+16); per-warp math identical to R7 (bit-exact).
// SMEM: K tile (9216) + V tile (9216) + mask (8192) = 26624.
#define ASMEM 26624
__global__ __launch_bounds__(256, 2) void attn_hmma(
    const __half* __restrict__ Qh, const __half* __restrict__ Kh,
    const __half* __restrict__ Vh, const float* __restrict__ mask,
    __half* __restrict__ Oh) {
  extern __shared__ char sm8[];
  const uint32_t smb = smem_u32(sm8);
  float* smask = (float*)(sm8 + 18432);
  const int t = threadIdx.x, wid = t >> 5, l = t & 31;
  const int qt = blockIdx.x, h = blockIdx.y, b = blockIdx.z;
  const int hc = h << 6, tokbase = b * SS, q0 = qt << 7;

  // stage mask * LOG2E (once)
  for (int i = t; i < SS / 4; i += 256) {
    float4 mv = ((const float4*)(mask + b * SS))[i];
    mv.x *= LOG2E; mv.y *= LOG2E; mv.z *= LOG2E; mv.w *= LOG2E;
    ((float4*)smask)[i] = mv;
  }

  // Q fragments resident in registers (warp w -> q rows [16w, 16w+16))
  const int grow0 = tokbase + q0 + (wid << 4) + (l >> 2);
  uint32_t qh[4][4];
#pragma unroll
  for (int kc = 0; kc < 4; kc++)
#pragma unroll
    for (int j = 0; j < 4; j++) {
      const int row = grow0 + ((j & 1) << 3);
      const int k = (kc << 4) + ((l & 3) << 1) + ((j >> 1) << 3);
      qh[kc][j] = *(const uint32_t*)(Qh + (size_t)row * HH + hc + k);
    }

  float o[8][4];
#pragma unroll
  for (int i = 0; i < 8; i++)
#pragma unroll
    for (int j = 0; j < 4; j++) o[i][j] = 0.f;
  float m1 = -1e30f, m2 = -1e30f, lsum1 = 0.f, lsum2 = 0.f;

  const int lr = t >> 3, lc = t & 7;   // 256 thr: 32 rows x 8 col-chunks, 2 passes
  const int krow = (l & 7) + ((l >> 4) << 3);
  const int kcol_off = ((l >> 3) & 1) << 3;
  const int vrow = (l & 7) + (((l >> 3) & 1) << 3);
  const int vcol = (l >> 4) << 3;
  const float sl = SCALE * LOG2E;

  uint4 pk[2], pv[2];
#define ALOAD(K0) do { \
  _Pragma("unroll") \
  for (int i = 0; i < 2; i++) { \
    const size_t g = (size_t)(tokbase + (K0) + lr + (i << 5)) * HH + hc + lc * 8; \
    pk[i] = *(const uint4*)(Kh + g); \
    pv[i] = *(const uint4*)(Vh + g); \
  } } while (0)

  ALOAD(0);
  for (int kt = 0; kt < SS / 64; kt++) {
    const int k0 = kt << 6;
    __syncthreads();
#pragma unroll
    for (int i = 0; i < 2; i++) {
      const uint32_t so = (uint32_t)((lr + (i << 5)) * 72 + lc * 8) * 2;
      *(uint4*)(sm8 + so)        = pk[i];
      *(uint4*)(sm8 + 9216 + so) = pv[i];
    }
    __syncthreads();
    if (kt < SS / 64 - 1) ALOAD(k0 + 64);

    // ---- S = Q @ K^T (single fp16) ----
    float sc[8][4];
#pragma unroll
    for (int i = 0; i < 8; i++)
#pragma unroll
      for (int j = 0; j < 4; j++) sc[i][j] = 0.f;
#pragma unroll
    for (int kc = 0; kc < 4; kc++) {
      uint32_t kh[16];
#pragma unroll
      for (int np = 0; np < 4; np++) {
        const uint32_t sk =
            smb + (uint32_t)(((np << 4) + krow) * 72 + (kc << 4) + kcol_off) * 2;
        ldsm4(kh + np * 4, sk);
      }
#pragma unroll
      for (int nt = 0; nt < 8; nt++)
        mma16816h(sc[nt], qh[kc], kh[nt*2], kh[nt*2+1]);
    }

    // ---- online softmax (log2 domain) ----
    float nm1 = m1, nm2 = m2;
#pragma unroll
    for (int nt = 0; nt < 8; nt++) {
      const float2 mv = *(const float2*)&smask[k0 + (nt << 3) + ((l & 3) << 1)];
      sc[nt][0] = sc[nt][0] * sl + mv.x;
      sc[nt][1] = sc[nt][1] * sl + mv.y;
      sc[nt][2] = sc[nt][2] * sl + mv.x;
      sc[nt][3] = sc[nt][3] * sl + mv.y;
      nm1 = fmaxf(nm1, fmaxf(sc[nt][0], sc[nt][1]));
      nm2 = fmaxf(nm2, fmaxf(sc[nt][2], sc[nt][3]));
    }
    nm1 = fmaxf(nm1, __shfl_xor_sync(0xffffffffu, nm1, 1));
    nm1 = fmaxf(nm1, __shfl_xor_sync(0xffffffffu, nm1, 2));
    nm2 = fmaxf(nm2, __shfl_xor_sync(0xffffffffu, nm2, 1));
    nm2 = fmaxf(nm2, __shfl_xor_sync(0xffffffffu, nm2, 2));
    const float a1 = exp2f(m1 - nm1), a2 = exp2f(m2 - nm2);
    m1 = nm1; m2 = nm2;
    float rs1 = 0.f, rs2 = 0.f;
#pragma unroll
    for (int nt = 0; nt < 8; nt++) {
      sc[nt][0] = exp2f(sc[nt][0] - m1);
      sc[nt][1] = exp2f(sc[nt][1] - m1);
      sc[nt][2] = exp2f(sc[nt][2] - m2);
      sc[nt][3] = exp2f(sc[nt][3] - m2);
      rs1 += sc[nt][0] + sc[nt][1];
      rs2 += sc[nt][2] + sc[nt][3];
      o[nt][0] *= a1; o[nt][1] *= a1; o[nt][2] *= a2; o[nt][3] *= a2;
    }
    lsum1 = lsum1 * a1 + rs1;
    lsum2 = lsum2 * a2 + rs2;

    // ---- O += P @ V (single fp16) ----
#pragma unroll
    for (int kc2 = 0; kc2 < 4; kc2++) {
      uint32_t ph[4];
      ph[0] = pack_h2(sc[2*kc2][0],   sc[2*kc2][1]);
      ph[1] = pack_h2(sc[2*kc2][2],   sc[2*kc2][3]);
      ph[2] = pack_h2(sc[2*kc2+1][0], sc[2*kc2+1][1]);
      ph[3] = pack_h2(sc[2*kc2+1][2], sc[2*kc2+1][3]);
#pragma unroll
      for (int dp = 0; dp < 4; dp++) {
        uint32_t vh[4];
        const uint32_t sv =
            smb + 9216 +
            (uint32_t)(((kc2 << 4) + vrow) * 72 + (dp << 4) + vcol) * 2;
        ldsm4t(vh, sv);
        mma16816h(o[2*dp],   ph, vh[0], vh[1]);
        mma16816h(o[2*dp+1], ph, vh[2], vh[3]);
      }
    }
  }
#undef ALOAD

  // ---- epilogue: normalize + store CTX fp16 ----
  lsum1 += __shfl_xor_sync(0xffffffffu, lsum1, 1);
  lsum1 += __shfl_xor_sync(0xffffffffu, lsum1, 2);
  lsum2 += __shfl_xor_sync(0xffffffffu, lsum2, 1);
  lsum2 += __shfl_xor_sync(0xffffffffu, lsum2, 2);
  const float i1 = 1.f / lsum1, i2 = 1.f / lsum2;
  const int r1 = grow0, r2 = grow0 + 8;
#pragma unroll
  for (int nt = 0; nt < 8; nt++) {
    const int col = hc + (nt << 3) + ((l & 3) << 1);
    *(uint32_t*)&Oh[(size_t)r1 * HH + col] =
        pack_h2(o[nt][0] * i1, o[nt][1] * i1);
    *(uint32_t*)&Oh[(size_t)r2 * HH + col] =
        pack_h2(o[nt][2] * i2, o[nt][3] * i2);
  }
}

// ---------------- launch ------------------------------------------------------
extern "C" void kernel_launch(void* const* d_in, const int* in_sizes, int n_in,
                              void* d_out, int out_size) {
  const float* x    = (const float*)d_in[0];
  const float* mask = (const float*)d_in[1];
  const float* Wq   = (const float*)d_in[2];
  const float* bq   = (const float*)d_in[3];
  const float* Wk   = (const float*)d_in[4];
  const float* bk   = (const float*)d_in[5];
  const float* Wv   = (const float*)d_in[6];
  const float* bv   = (const float*)d_in[7];
  const float* Wql  = (const float*)d_in[8];
  const float* bql  = (const float*)d_in[9];
  const float* Wkl  = (const float*)d_in[10];
  const float* bkl  = (const float*)d_in[11];
  const float* Wo   = (const float*)d_in[12];
  const float* bo   = (const float*)d_in[13];
  float* out = (float*)d_out;

  float *WqF, *WkF, *bqF, *bkF;
  cudaGetSymbolAddress((void**)&WqF, g_WqF);
  cudaGetSymbolAddress((void**)&WkF, g_WkF);
  cudaGetSymbolAddress((void**)&bqF, g_bqF);
  cudaGetSymbolAddress((void**)&bkF, g_bkF);
  __half *xh, *Qhp, *Khp, *Vhp, *Chp, *Bqp, *Bkp, *Bvp, *Bop;
  cudaGetSymbolAddress((void**)&xh, g_xh);
  cudaGetSymbolAddress((void**)&Qhp, g_Qh);
  cudaGetSymbolAddress((void**)&Khp, g_Kh);
  cudaGetSymbolAddress((void**)&Vhp, g_Vh);
  cudaGetSymbolAddress((void**)&Chp, g_Ch);
  cudaGetSymbolAddress((void**)&Bqp, g_Bq);
  cudaGetSymbolAddress((void**)&Bkp, g_Bk);
  cudaGetSymbolAddress((void**)&Bvp, g_Bv);
  cudaGetSymbolAddress((void**)&Bop, g_Bo);

  cudaFuncSetAttribute(qkv_hmma,
                       cudaFuncAttributeMaxDynamicSharedMemorySize, GSMEM);
  cudaFuncSetAttribute(gemmo_hmma,
                       cudaFuncAttributeMaxDynamicSharedMemorySize, GSMEM);
  cudaFuncSetAttribute(attn_hmma,
                       cudaFuncAttributeMaxDynamicSharedMemorySize, ASMEM);

  // 1. fold low-rank projections into token-GEMM weights (batched q/k)
  fold_w_kernel<<<dim3(NH, 16, 2), 256>>>(Wq, Wql, Wk, Wkl, WqF, WkF);
  fold_b_kernel<<<dim3(4, 1, 2), 256>>>(bq, Wql, bql, bk, Wkl, bkl, bqF, bkF);

  // 2. x -> fp16; weights -> transposed fp16 (batched 4)
  cvt_kernel<<<(MM*HH/4 + 255)/256, 256>>>(x, xh, MM*HH/4);
  tcvt_kernel<<<dim3(32, 32, 4), 256>>>(WqF, WkF, Wv, Wo, Bqp, Bkp, Bvp, Bop);

  // 3. merged QKV projection (R7-proven 128x64 tiles, reg-prefetch)
  qkv_hmma<<<dim3(16, 32, 3), 256, GSMEM>>>(
      xh, Bqp, Bkp, Bvp, bqF, bkF, bv, Qhp, Khp, Vhp);

  // 4. fp16 flash attention (128-q tiles, 256 thr) -> CTX fp16
  attn_hmma<<<dim3(SS/128, NH, BB), 256, ASMEM>>>(Qhp, Khp, Vhp, mask, Chp);

  // 5. output projection (fp32 out)
  gemmo_hmma<<<dim3(16, 32), 256, GSMEM>>>(Chp, Bop, bo, out);
}